// round 5
// baseline (speedup 1.0000x reference)
#include <cuda_runtime.h>

// ---------------------------------------------------------------------------
// GATv2 x2 + BatchNorm GNN, GB300 (sm_103a), fp32 pipeline.
//
// Inputs (metadata order):
//  0 x[10000*165] 1 gamma1[165] 2 beta1[165] 3 Wl1[165*1024] 4 bl1[1024]
//  5 Wr1[165*1024] 6 br1[1024] 7 att1[8*128] 8 bias1[1024]
//  9 gamma2[1024] 10 beta2[1024] 11 Wl2[1024*8] 12 bl2[8] 13 Wr2[1024*8]
// 14 br2[8] 15 att2[8] 16 bias2[1] 17 edge_index[2*160000] (int32)
// Output: [10000] float (GAT2 head-mean + bias2)
// ---------------------------------------------------------------------------

#define NN     10000     // nodes
#define EIN    160000    // input edges
#define ETOT   170000    // + self loops
#define DIN    165
#define HID    1024
#define NH     8
#define C1     128

// ----------------------------- scratch (no allocs allowed) -----------------
__device__ float g_xbn [NN * DIN];
__device__ float g_stat1[2 * DIN];        // col sum, sumsq of x
__device__ float g_xl1 [NN * HID];
__device__ float g_xr1 [NN * HID];
__device__ float g_log1[ETOT * NH];       // logits -> alpha (in place)
__device__ float g_h1  [NN * HID];        // GAT1 output
__device__ float g_stat2[2 * HID];        // col sum, sumsq of h1 (atomics)
__device__ float g_h2  [NN * HID];        // BN2 + leaky(0.01)
__device__ float g_xl2 [NN * NH];
__device__ float g_xr2 [NN * NH];
__device__ float g_log2[ETOT * NH];
__device__ int   g_deg   [NN];
__device__ int   g_rowptr[NN + 1];
__device__ int   g_cursor[NN];
__device__ int   g_eidx  [ETOT];          // edge id per CSR slot
__device__ int   g_esrc  [ETOT];          // src node per CSR slot

// ----------------------------- tiny helpers --------------------------------
__device__ __forceinline__ float leaky(float v, float s) { return v > 0.f ? v : s * v; }

// ============================ 0) zero scratch ===============================
__global__ void k_zero()
{
    int i = blockIdx.x * blockDim.x + threadIdx.x;
    if (i < 2 * HID) g_stat2[i] = 0.f;
    if (i < NN)      g_deg[i] = 0;
}

// ============================ 1) BN1 stats ==================================
// one block per column (165 blocks)
__global__ __launch_bounds__(256) void k_bn1_stats(const float* __restrict__ x)
{
    int c = blockIdx.x, t = threadIdx.x;
    float s = 0.f, q = 0.f;
    for (int r = t; r < NN; r += 256) {
        float v = x[r * DIN + c];
        s += v; q += v * v;
    }
    __shared__ float ss[256], qq[256];
    ss[t] = s; qq[t] = q; __syncthreads();
    for (int o = 128; o; o >>= 1) {
        if (t < o) { ss[t] += ss[t + o]; qq[t] += qq[t + o]; }
        __syncthreads();
    }
    if (t == 0) { g_stat1[c] = ss[0]; g_stat1[DIN + c] = qq[0]; }
}

// ============================ 2) BN1 normalize ==============================
__global__ void k_bn1_norm(const float* __restrict__ x,
                           const float* __restrict__ gamma,
                           const float* __restrict__ beta)
{
    int idx = blockIdx.x * blockDim.x + threadIdx.x;
    if (idx >= NN * DIN) return;
    int c = idx % DIN;
    float mu  = g_stat1[c] * (1.f / NN);
    float var = g_stat1[DIN + c] * (1.f / NN) - mu * mu;
    float rs  = rsqrtf(var + 1e-5f);
    g_xbn[idx] = (x[idx] - mu) * rs * gamma[c] + beta[c];
}

// ============================ 3) GEMM1 ======================================
// C[10000, 2048] = xbn @ [Wl1 | Wr1], + [bl1 | br1] -> xl1 / xr1
#define BM 128
#define BNN 128
#define BK 8
__global__ __launch_bounds__(256) void k_gemm1(const float* __restrict__ Wl,
                                               const float* __restrict__ bl,
                                               const float* __restrict__ Wr,
                                               const float* __restrict__ br)
{
    __shared__ float As[BK][BM];
    __shared__ float Bs[BK][BNN];
    int tid = threadIdx.x;
    int tx = tid & 15, ty = tid >> 4;          // 16x16 threads, 8x8 microtile
    int row0 = blockIdx.y * BM;
    int col0 = blockIdx.x * BNN;               // uniform: all <HID or all >=HID
    int ar = tid >> 1, ak0 = (tid & 1) * 4;    // A loader
    int bk = tid >> 5, bc = (tid & 31) * 4;    // B loader
    float acc[8][8];
#pragma unroll
    for (int i = 0; i < 8; i++)
#pragma unroll
        for (int j = 0; j < 8; j++) acc[i][j] = 0.f;

    for (int kt = 0; kt < DIN; kt += BK) {
        int r = row0 + ar;
#pragma unroll
        for (int i = 0; i < 4; i++) {
            int k = kt + ak0 + i;
            As[ak0 + i][ar] = (k < DIN && r < NN) ? g_xbn[r * DIN + k] : 0.f;
        }
        int kB = kt + bk;
#pragma unroll
        for (int i = 0; i < 4; i++) {
            int c = col0 + bc + i;
            float v = 0.f;
            if (kB < DIN)
                v = (c < HID) ? Wl[kB * HID + c] : Wr[kB * HID + (c - HID)];
            Bs[bk][bc + i] = v;
        }
        __syncthreads();
#pragma unroll
        for (int k = 0; k < BK; k++) {
            float4 a0 = *(const float4*)&As[k][ty * 8];
            float4 a1 = *(const float4*)&As[k][ty * 8 + 4];
            float4 b0 = *(const float4*)&Bs[k][tx * 8];
            float4 b1 = *(const float4*)&Bs[k][tx * 8 + 4];
            float av[8] = {a0.x,a0.y,a0.z,a0.w,a1.x,a1.y,a1.z,a1.w};
            float bv[8] = {b0.x,b0.y,b0.z,b0.w,b1.x,b1.y,b1.z,b1.w};
#pragma unroll
            for (int i = 0; i < 8; i++)
#pragma unroll
                for (int j = 0; j < 8; j++) acc[i][j] += av[i] * bv[j];
        }
        __syncthreads();
    }
#pragma unroll
    for (int i = 0; i < 8; i++) {
        int r = row0 + ty * 8 + i;
        if (r >= NN) continue;
#pragma unroll
        for (int j = 0; j < 8; j++) {
            int c = col0 + tx * 8 + j;
            float v = acc[i][j];
            if (c < HID) g_xl1[r * HID + c]         = v + bl[c];
            else         g_xr1[r * HID + (c - HID)] = v + br[c - HID];
        }
    }
}

// ============================ 4) CSR build ==================================
__global__ void k_count(const int* __restrict__ ei)
{
    int e = blockIdx.x * blockDim.x + threadIdx.x;
    if (e >= ETOT) return;
    int dst = (e < EIN) ? ei[EIN + e] : (e - EIN);
    atomicAdd(&g_deg[dst], 1);
}

__global__ __launch_bounds__(1024) void k_scan()
{
    const int CH = 10;                        // 1024*10 >= 10000
    int t = threadIdx.x;
    int base = t * CH;
    int local[CH]; int s = 0;
#pragma unroll
    for (int i = 0; i < CH; i++) {
        int idx = base + i;
        int v = (idx < NN) ? g_deg[idx] : 0;
        local[i] = s; s += v;
    }
    int lane = t & 31, wid = t >> 5;
    int inc = s;
#pragma unroll
    for (int o = 1; o < 32; o <<= 1) {
        int u = __shfl_up_sync(0xffffffffu, inc, o);
        if (lane >= o) inc += u;
    }
    __shared__ int wsum[32];
    if (lane == 31) wsum[wid] = inc;
    __syncthreads();
    if (wid == 0) {
        int v = wsum[lane];
#pragma unroll
        for (int o = 1; o < 32; o <<= 1) {
            int u = __shfl_up_sync(0xffffffffu, v, o);
            if (lane >= o) v += u;
        }
        wsum[lane] = v;
    }
    __syncthreads();
    int excl = inc - s + (wid > 0 ? wsum[wid - 1] : 0);
#pragma unroll
    for (int i = 0; i < CH; i++) {
        int idx = base + i;
        if (idx < NN) { g_rowptr[idx] = excl + local[i]; g_cursor[idx] = excl + local[i]; }
    }
    if (t == 1023) g_rowptr[NN] = excl + s;
}

__global__ void k_scatter(const int* __restrict__ ei)
{
    int e = blockIdx.x * blockDim.x + threadIdx.x;
    if (e >= ETOT) return;
    int src, dst;
    if (e < EIN) { src = ei[e]; dst = ei[EIN + e]; }
    else         { src = e - EIN; dst = src; }
    int pos = atomicAdd(&g_cursor[dst], 1);
    g_eidx[pos] = e;
    g_esrc[pos] = src;
}

// ============================ 5) edge logits L1 =============================
// one warp per edge; iteration h covers exactly head h (128 ch = 32 lanes x f4)
__global__ __launch_bounds__(256) void k_logits1(const int* __restrict__ ei,
                                                 const float* __restrict__ att)
{
    int w = (blockIdx.x * blockDim.x + threadIdx.x) >> 5;
    int lane = threadIdx.x & 31;
    if (w >= ETOT) return;
    int e = w;
    int src, dst;
    if (e < EIN) { src = ei[e]; dst = ei[EIN + e]; }
    else         { src = e - EIN; dst = src; }
    const float4* pl = (const float4*)(g_xl1 + src * HID);
    const float4* pr = (const float4*)(g_xr1 + dst * HID);
    const float4* pa = (const float4*)att;
#pragma unroll
    for (int h = 0; h < NH; h++) {
        float4 a = pl[h * 32 + lane];
        float4 b = pr[h * 32 + lane];
        float4 wv = pa[h * 32 + lane];
        float v0 = leaky(a.x + b.x, 0.2f);
        float v1 = leaky(a.y + b.y, 0.2f);
        float v2 = leaky(a.z + b.z, 0.2f);
        float v3 = leaky(a.w + b.w, 0.2f);
        float s = v0 * wv.x + v1 * wv.y + v2 * wv.z + v3 * wv.w;
#pragma unroll
        for (int o = 16; o; o >>= 1) s += __shfl_xor_sync(0xffffffffu, s, o);
        if (lane == 0) g_log1[e * NH + h] = s;
    }
}

// ============================ 6) segment softmax (both layers) ==============
// one warp per node; 3 CSR passes: max, sum, write alpha in place
__global__ __launch_bounds__(256) void k_softmax(int which)
{
    float* logit = which ? g_log2 : g_log1;
    int n = (blockIdx.x * blockDim.x + threadIdx.x) >> 5;
    int lane = threadIdx.x & 31;
    if (n >= NN) return;
    int beg = g_rowptr[n], end = g_rowptr[n + 1];
    float m[NH];
#pragma unroll
    for (int h = 0; h < NH; h++) m[h] = -1e30f;
    for (int s = beg + lane; s < end; s += 32) {
        const float4* p = (const float4*)(logit + g_eidx[s] * NH);
        float4 a = p[0], b = p[1];
        m[0] = fmaxf(m[0], a.x); m[1] = fmaxf(m[1], a.y);
        m[2] = fmaxf(m[2], a.z); m[3] = fmaxf(m[3], a.w);
        m[4] = fmaxf(m[4], b.x); m[5] = fmaxf(m[5], b.y);
        m[6] = fmaxf(m[6], b.z); m[7] = fmaxf(m[7], b.w);
    }
#pragma unroll
    for (int h = 0; h < NH; h++)
#pragma unroll
        for (int o = 16; o; o >>= 1)
            m[h] = fmaxf(m[h], __shfl_xor_sync(0xffffffffu, m[h], o));
    float sum[NH];
#pragma unroll
    for (int h = 0; h < NH; h++) sum[h] = 0.f;
    for (int s = beg + lane; s < end; s += 32) {
        const float4* p = (const float4*)(logit + g_eidx[s] * NH);
        float4 a = p[0], b = p[1];
        sum[0] += __expf(a.x - m[0]); sum[1] += __expf(a.y - m[1]);
        sum[2] += __expf(a.z - m[2]); sum[3] += __expf(a.w - m[3]);
        sum[4] += __expf(b.x - m[4]); sum[5] += __expf(b.y - m[5]);
        sum[6] += __expf(b.z - m[6]); sum[7] += __expf(b.w - m[7]);
    }
#pragma unroll
    for (int h = 0; h < NH; h++) {
#pragma unroll
        for (int o = 16; o; o >>= 1)
            sum[h] += __shfl_xor_sync(0xffffffffu, sum[h], o);
        sum[h] = 1.f / (sum[h] + 1e-16f);
    }
    for (int s = beg + lane; s < end; s += 32) {
        float4* p = (float4*)(logit + g_eidx[s] * NH);
        float4 a = p[0], b = p[1];
        a.x = __expf(a.x - m[0]) * sum[0]; a.y = __expf(a.y - m[1]) * sum[1];
        a.z = __expf(a.z - m[2]) * sum[2]; a.w = __expf(a.w - m[3]) * sum[3];
        b.x = __expf(b.x - m[4]) * sum[4]; b.y = __expf(b.y - m[5]) * sum[5];
        b.z = __expf(b.z - m[6]) * sum[6]; b.w = __expf(b.w - m[7]) * sum[7];
        p[0] = a; p[1] = b;
    }
}

// ============================ 7) aggregation L1 =============================
// one block (256 thr) per node; thread owns 4 channels (same head per warp)
__global__ __launch_bounds__(256) void k_agg1(const float* __restrict__ bias)
{
    int i = blockIdx.x;
    int t = threadIdx.x;
    int c0 = t * 4;
    int h = c0 >> 7;                           // uniform per warp
    int beg = g_rowptr[i], end = g_rowptr[i + 1];
    float4 acc = {0.f, 0.f, 0.f, 0.f};
    for (int s = beg; s < end; s++) {
        int e = g_eidx[s];
        int src = g_esrc[s];
        float al = g_log1[e * NH + h];         // broadcast within warp
        float4 v = *(const float4*)(g_xl1 + src * HID + c0);
        acc.x += al * v.x; acc.y += al * v.y;
        acc.z += al * v.z; acc.w += al * v.w;
    }
    float4 b = *(const float4*)(bias + c0);
    acc.x += b.x; acc.y += b.y; acc.z += b.z; acc.w += b.w;
    *(float4*)(g_h1 + i * HID + c0) = acc;
}

// ============================ 8) BN2 stats ==================================
// block handles 128 rows, coalesced; partial sums -> global atomics (per col)
__global__ __launch_bounds__(256) void k_bn2_stats()
{
    int r0 = blockIdx.x * 128;
    int t = threadIdx.x;
    float s[4] = {0,0,0,0}, q[4] = {0,0,0,0};
    int rmax = min(128, NN - r0);
    for (int r = 0; r < rmax; r++) {
        const float* row = g_h1 + (r0 + r) * HID;
#pragma unroll
        for (int j = 0; j < 4; j++) {
            float v = row[t + j * 256];
            s[j] += v; q[j] += v * v;
        }
    }
#pragma unroll
    for (int j = 0; j < 4; j++) {
        atomicAdd(&g_stat2[t + j * 256], s[j]);
        atomicAdd(&g_stat2[HID + t + j * 256], q[j]);
    }
}

// ============================ 9) BN2 norm + leaky(0.01) =====================
__global__ void k_bn2_norm(const float* __restrict__ gamma,
                           const float* __restrict__ beta)
{
    int i4 = blockIdx.x * blockDim.x + threadIdx.x;
    if (i4 >= NN * HID / 4) return;
    int c4 = i4 & (HID / 4 - 1);
    float4 v = ((const float4*)g_h1)[i4];
    float4 su = ((const float4*)g_stat2)[c4];
    float4 sq = ((const float4*)(g_stat2 + HID))[c4];
    float4 gm = ((const float4*)gamma)[c4];
    float4 bt = ((const float4*)beta)[c4];
    float mu, var, rs, o;
    float4 r;
    mu = su.x * (1.f/NN); var = sq.x * (1.f/NN) - mu*mu; rs = rsqrtf(var + 1e-5f);
    o = (v.x - mu) * rs * gm.x + bt.x; r.x = leaky(o, 0.01f);
    mu = su.y * (1.f/NN); var = sq.y * (1.f/NN) - mu*mu; rs = rsqrtf(var + 1e-5f);
    o = (v.y - mu) * rs * gm.y + bt.y; r.y = leaky(o, 0.01f);
    mu = su.z * (1.f/NN); var = sq.z * (1.f/NN) - mu*mu; rs = rsqrtf(var + 1e-5f);
    o = (v.z - mu) * rs * gm.z + bt.z; r.z = leaky(o, 0.01f);
    mu = su.w * (1.f/NN); var = sq.w * (1.f/NN) - mu*mu; rs = rsqrtf(var + 1e-5f);
    o = (v.w - mu) * rs * gm.w + bt.w; r.w = leaky(o, 0.01f);
    ((float4*)g_h2)[i4] = r;
}

// ============================ 10) GEMM2 (tall-skinny) =======================
// warp per row: xl2 = h2 @ Wl2 + bl2 ; xr2 = h2 @ Wr2 + br2
__global__ __launch_bounds__(256) void k_gemm2(const float* __restrict__ Wl,
                                               const float* __restrict__ bl,
                                               const float* __restrict__ Wr,
                                               const float* __restrict__ br)
{
    int rw = (blockIdx.x * blockDim.x + threadIdx.x) >> 5;
    int lane = threadIdx.x & 31;
    if (rw >= NN) return;
    const float* row = g_h2 + rw * HID;
    float acc[16];
#pragma unroll
    for (int j = 0; j < 16; j++) acc[j] = 0.f;
    for (int k = lane; k < HID; k += 32) {
        float a = row[k];
        float4 w0 = ((const float4*)(Wl + k * 8))[0];
        float4 w1 = ((const float4*)(Wl + k * 8))[1];
        float4 u0 = ((const float4*)(Wr + k * 8))[0];
        float4 u1 = ((const float4*)(Wr + k * 8))[1];
        acc[0] += a*w0.x; acc[1] += a*w0.y; acc[2] += a*w0.z; acc[3] += a*w0.w;
        acc[4] += a*w1.x; acc[5] += a*w1.y; acc[6] += a*w1.z; acc[7] += a*w1.w;
        acc[8] += a*u0.x; acc[9] += a*u0.y; acc[10]+= a*u0.z; acc[11]+= a*u0.w;
        acc[12]+= a*u1.x; acc[13]+= a*u1.y; acc[14]+= a*u1.z; acc[15]+= a*u1.w;
    }
#pragma unroll
    for (int j = 0; j < 16; j++)
#pragma unroll
        for (int o = 16; o; o >>= 1)
            acc[j] += __shfl_xor_sync(0xffffffffu, acc[j], o);
    if (lane < 8)       g_xl2[rw * 8 + lane]       = acc[lane] + bl[lane];
    else if (lane < 16) g_xr2[rw * 8 + (lane - 8)] = acc[lane] + br[lane - 8];
}

// ============================ 11) edge logits L2 ============================
__global__ void k_logits2(const int* __restrict__ ei,
                          const float* __restrict__ att)
{
    int e = blockIdx.x * blockDim.x + threadIdx.x;
    if (e >= ETOT) return;
    int src, dst;
    if (e < EIN) { src = ei[e]; dst = ei[EIN + e]; }
    else         { src = e - EIN; dst = src; }
    float4 l0 = ((const float4*)(g_xl2 + src * 8))[0];
    float4 l1 = ((const float4*)(g_xl2 + src * 8))[1];
    float4 r0 = ((const float4*)(g_xr2 + dst * 8))[0];
    float4 r1 = ((const float4*)(g_xr2 + dst * 8))[1];
    float4 a0 = ((const float4*)att)[0];
    float4 a1 = ((const float4*)att)[1];
    float4 o0, o1;
    o0.x = leaky(l0.x + r0.x, 0.2f) * a0.x;
    o0.y = leaky(l0.y + r0.y, 0.2f) * a0.y;
    o0.z = leaky(l0.z + r0.z, 0.2f) * a0.z;
    o0.w = leaky(l0.w + r0.w, 0.2f) * a0.w;
    o1.x = leaky(l1.x + r1.x, 0.2f) * a1.x;
    o1.y = leaky(l1.y + r1.y, 0.2f) * a1.y;
    o1.z = leaky(l1.z + r1.z, 0.2f) * a1.z;
    o1.w = leaky(l1.w + r1.w, 0.2f) * a1.w;
    ((float4*)(g_log2 + e * 8))[0] = o0;
    ((float4*)(g_log2 + e * 8))[1] = o1;
}

// ============================ 12) aggregation L2 + head mean ================
__global__ void k_agg2(const float* __restrict__ bias2, float* __restrict__ out)
{
    int i = blockIdx.x * blockDim.x + threadIdx.x;
    if (i >= NN) return;
    int beg = g_rowptr[i], end = g_rowptr[i + 1];
    float a0 = 0, a1 = 0, a2 = 0, a3 = 0, a4 = 0, a5 = 0, a6 = 0, a7 = 0;
    for (int s = beg; s < end; s++) {
        int e = g_eidx[s];
        int src = g_esrc[s];
        float4 p0 = ((const float4*)(g_log2 + e * 8))[0];
        float4 p1 = ((const float4*)(g_log2 + e * 8))[1];
        float4 v0 = ((const float4*)(g_xl2 + src * 8))[0];
        float4 v1 = ((const float4*)(g_xl2 + src * 8))[1];
        a0 += p0.x * v0.x; a1 += p0.y * v0.y; a2 += p0.z * v0.z; a3 += p0.w * v0.w;
        a4 += p1.x * v1.x; a5 += p1.y * v1.y; a6 += p1.z * v1.z; a7 += p1.w * v1.w;
    }
    float s8 = (a0 + a1 + a2 + a3 + a4 + a5 + a6 + a7) * 0.125f;
    out[i] = s8 + bias2[0];
}

// ============================ launch ========================================
extern "C" void kernel_launch(void* const* d_in, const int* in_sizes, int n_in,
                              void* d_out, int out_size)
{
    const float* x      = (const float*)d_in[0];
    const float* gamma1 = (const float*)d_in[1];
    const float* beta1  = (const float*)d_in[2];
    const float* Wl1    = (const float*)d_in[3];
    const float* bl1    = (const float*)d_in[4];
    const float* Wr1    = (const float*)d_in[5];
    const float* br1    = (const float*)d_in[6];
    const float* att1   = (const float*)d_in[7];
    const float* bias1  = (const float*)d_in[8];
    const float* gamma2 = (const float*)d_in[9];
    const float* beta2  = (const float*)d_in[10];
    const float* Wl2    = (const float*)d_in[11];
    const float* bl2    = (const float*)d_in[12];
    const float* Wr2    = (const float*)d_in[13];
    const float* br2    = (const float*)d_in[14];
    const float* att2   = (const float*)d_in[15];
    const float* bias2  = (const float*)d_in[16];
    const int*   ei     = (const int*)  d_in[17];
    float* out = (float*)d_out;

    k_zero<<<(NN + 255) / 256, 256>>>();
    k_bn1_stats<<<DIN, 256>>>(x);
    k_bn1_norm<<<(NN * DIN + 255) / 256, 256>>>(x, gamma1, beta1);
    k_gemm1<<<dim3(2048 / BNN, (NN + BM - 1) / BM), 256>>>(Wl1, bl1, Wr1, br1);

    k_count<<<(ETOT + 255) / 256, 256>>>(ei);
    k_scan<<<1, 1024>>>();
    k_scatter<<<(ETOT + 255) / 256, 256>>>(ei);

    k_logits1<<<(ETOT * 32 + 255) / 256, 256>>>(ei, att1);
    k_softmax<<<(NN * 32 + 255) / 256, 256>>>(0);
    k_agg1<<<NN, 256>>>(bias1);

    k_bn2_stats<<<(NN + 127) / 128, 256>>>();
    k_bn2_norm<<<(NN * HID / 4 + 255) / 256, 256>>>(gamma2, beta2);

    k_gemm2<<<(NN * 32 + 255) / 256, 256>>>(Wl2, bl2, Wr2, br2);
    k_logits2<<<(ETOT + 255) / 256, 256>>>(ei, att2);
    k_softmax<<<(NN * 32 + 255) / 256, 256>>>(1);
    k_agg2<<<(NN + 255) / 256, 256>>>(bias2, out);
}

// round 10
// speedup vs baseline: 1.3356x; 1.3356x over previous
#include <cuda_runtime.h>
#include <cuda_bf16.h>
#include <cstdint>

// ---------------------------------------------------------------------------
// GATv2 x2 + BatchNorm GNN, GB300 (sm_103a).
// GEMM1 via mma.sync bf16 (2-way split, fp32 accum) — baseline PTX, no
// arch-specific ('a') instructions (ptxas target here is plain sm_103).
// ---------------------------------------------------------------------------

#define NN     10000     // nodes
#define NPAD   10112     // 79 * 128
#define EIN    160000    // input edges
#define ETOT   170000    // + self loops
#define DIN    165
#define KPAD   192       // DIN padded to 6 chunks of 32
#define HID    1024
#define NH     8

// ----------------------------- scratch (no allocs allowed) -----------------
__device__ __nv_bfloat16 g_a_hi[NPAD * KPAD];   // BN1(x) split hi   [row][k]
__device__ __nv_bfloat16 g_a_lo[NPAD * KPAD];   // BN1(x) split lo
__device__ __nv_bfloat16 g_w_hi[2048 * KPAD];   // [Wl1|Wr1]^T hi    [n][k]
__device__ __nv_bfloat16 g_w_lo[2048 * KPAD];
__device__ float g_stat1[2 * DIN];
__device__ float g_xl1 [NN * HID];
__device__ float g_xr1 [NN * HID];
__device__ float g_log1[ETOT * NH];
__device__ float g_h1  [NN * HID];
__device__ float g_stat2[2 * HID];
__device__ float g_h2  [NN * HID];
__device__ float g_xl2 [NN * NH];
__device__ float g_xr2 [NN * NH];
__device__ float g_log2[ETOT * NH];
__device__ int   g_deg   [NN];
__device__ int   g_rowptr[NN + 1];
__device__ int   g_cursor[NN];
__device__ int   g_eidx  [ETOT];
__device__ int   g_esrc  [ETOT];

__device__ __forceinline__ float leaky(float v, float s) { return v > 0.f ? v : s * v; }

// ============================ 0) zero scratch ===============================
__global__ void k_zero()
{
    int i = blockIdx.x * blockDim.x + threadIdx.x;
    if (i < 2 * HID) g_stat2[i] = 0.f;
    if (i < NN)      g_deg[i] = 0;
}

// ============================ 1) BN1 stats ==================================
__global__ __launch_bounds__(256) void k_bn1_stats(const float* __restrict__ x)
{
    int c = blockIdx.x, t = threadIdx.x;
    float s = 0.f, q = 0.f;
    for (int r = t; r < NN; r += 256) {
        float v = x[r * DIN + c];
        s += v; q += v * v;
    }
    __shared__ float ss[256], qq[256];
    ss[t] = s; qq[t] = q; __syncthreads();
    for (int o = 128; o; o >>= 1) {
        if (t < o) { ss[t] += ss[t + o]; qq[t] += qq[t + o]; }
        __syncthreads();
    }
    if (t == 0) { g_stat1[c] = ss[0]; g_stat1[DIN + c] = qq[0]; }
}

// ============================ 2) BN1 normalize + bf16 split =================
__global__ void k_bn1_split(const float* __restrict__ x,
                            const float* __restrict__ gamma,
                            const float* __restrict__ beta)
{
    int idx = blockIdx.x * blockDim.x + threadIdx.x;
    if (idx >= NPAD * KPAD) return;
    int r = idx / KPAD;
    int k = idx - r * KPAD;
    float val = 0.f;
    if (r < NN && k < DIN) {
        float mu  = g_stat1[k] * (1.f / NN);
        float var = g_stat1[DIN + k] * (1.f / NN) - mu * mu;
        float rs  = rsqrtf(var + 1e-5f);
        val = (x[r * DIN + k] - mu) * rs * gamma[k] + beta[k];
    }
    __nv_bfloat16 hi = __float2bfloat16(val);
    __nv_bfloat16 lo = __float2bfloat16(val - __bfloat162float(hi));
    g_a_hi[idx] = hi;
    g_a_lo[idx] = lo;
}

// ============================ 2b) W transpose + split =======================
__global__ void k_wsplit(const float* __restrict__ Wl, const float* __restrict__ Wr)
{
    int idx = blockIdx.x * blockDim.x + threadIdx.x;
    if (idx >= 2048 * KPAD) return;
    int n = idx / KPAD;
    int k = idx - n * KPAD;
    float val = 0.f;
    if (k < DIN)
        val = (n < HID) ? Wl[k * HID + n] : Wr[k * HID + (n - HID)];
    __nv_bfloat16 hi = __float2bfloat16(val);
    __nv_bfloat16 lo = __float2bfloat16(val - __bfloat162float(hi));
    g_w_hi[idx] = hi;
    g_w_lo[idx] = lo;
}

// ============================ 3) GEMM1 via mma.sync =========================
// CTA = 128x128 tile, 8 warps (2x4), warp tile 64x32.
// K: 6 chunks of 32. D = Ah*Bh + Ah*Bl + Al*Bh in fp32.
#define GSTRIDE 40   // smem row stride in bf16 (32 data + 8 pad, conflict-free)

__device__ __forceinline__ void mma16816(float* c, const uint32_t* a, const uint32_t* b)
{
    asm volatile(
        "mma.sync.aligned.m16n8k16.row.col.f32.bf16.bf16.f32 "
        "{%0,%1,%2,%3}, {%4,%5,%6,%7}, {%8,%9}, {%0,%1,%2,%3};"
        : "+f"(c[0]), "+f"(c[1]), "+f"(c[2]), "+f"(c[3])
        : "r"(a[0]), "r"(a[1]), "r"(a[2]), "r"(a[3]), "r"(b[0]), "r"(b[1]));
}

__global__ __launch_bounds__(256) void k_gemm1_mma(const float* __restrict__ bl,
                                                   const float* __restrict__ br)
{
    __shared__ __align__(16) __nv_bfloat16 sAh[128 * GSTRIDE];
    __shared__ __align__(16) __nv_bfloat16 sAl[128 * GSTRIDE];
    __shared__ __align__(16) __nv_bfloat16 sBh[128 * GSTRIDE];
    __shared__ __align__(16) __nv_bfloat16 sBl[128 * GSTRIDE];

    int tid = threadIdx.x;
    int wid = tid >> 5, lane = tid & 31;
    int wr = wid & 1, wc = wid >> 1;            // warp grid 2 x 4
    int qrow = lane >> 2;                       // groupID 0..7
    int qk   = (lane & 3) * 2;                  // 0,2,4,6
    int row0 = blockIdx.y * 128;
    int col0 = blockIdx.x * 128;

    float acc[4][4][4];
#pragma unroll
    for (int mf = 0; mf < 4; mf++)
#pragma unroll
        for (int nf = 0; nf < 4; nf++)
#pragma unroll
            for (int j = 0; j < 4; j++) acc[mf][nf][j] = 0.f;

    const __nv_bfloat16* pAh = g_a_hi + (size_t)row0 * KPAD;
    const __nv_bfloat16* pAl = g_a_lo + (size_t)row0 * KPAD;
    const __nv_bfloat16* pBh = g_w_hi + (size_t)col0 * KPAD;
    const __nv_bfloat16* pBl = g_w_lo + (size_t)col0 * KPAD;

    for (int c = 0; c < 6; c++) {
        // ---- load chunk [128 rows x 32 bf16] per tile, uint4 granules ----
#pragma unroll
        for (int i = 0; i < 2; i++) {
            int flat = i * 256 + tid;           // 512 uint4 slots
            int row = flat >> 2, q = flat & 3;
            size_t go = (size_t)row * KPAD + c * 32 + q * 8;
            int so = row * GSTRIDE + q * 8;
            *(uint4*)(sAh + so) = *(const uint4*)(pAh + go);
            *(uint4*)(sAl + so) = *(const uint4*)(pAl + go);
            *(uint4*)(sBh + so) = *(const uint4*)(pBh + go);
            *(uint4*)(sBl + so) = *(const uint4*)(pBl + go);
        }
        __syncthreads();

#pragma unroll
        for (int ks = 0; ks < 32; ks += 16) {
            uint32_t bh[4][2], blr[4][2];
#pragma unroll
            for (int nf = 0; nf < 4; nf++) {
                int n = wc * 32 + nf * 8 + qrow;
                const __nv_bfloat16* bp = sBh + n * GSTRIDE + ks + qk;
                const __nv_bfloat16* lp = sBl + n * GSTRIDE + ks + qk;
                bh[nf][0]  = *(const uint32_t*)bp;
                bh[nf][1]  = *(const uint32_t*)(bp + 8);
                blr[nf][0] = *(const uint32_t*)lp;
                blr[nf][1] = *(const uint32_t*)(lp + 8);
            }
#pragma unroll
            for (int mf = 0; mf < 4; mf++) {
                int m = wr * 64 + mf * 16 + qrow;
                const __nv_bfloat16* ap = sAh + m * GSTRIDE + ks + qk;
                const __nv_bfloat16* lp = sAl + m * GSTRIDE + ks + qk;
                uint32_t ah[4], al[4];
                ah[0] = *(const uint32_t*)ap;
                ah[1] = *(const uint32_t*)(ap + 8 * GSTRIDE);
                ah[2] = *(const uint32_t*)(ap + 8);
                ah[3] = *(const uint32_t*)(ap + 8 * GSTRIDE + 8);
                al[0] = *(const uint32_t*)lp;
                al[1] = *(const uint32_t*)(lp + 8 * GSTRIDE);
                al[2] = *(const uint32_t*)(lp + 8);
                al[3] = *(const uint32_t*)(lp + 8 * GSTRIDE + 8);
#pragma unroll
                for (int nf = 0; nf < 4; nf++) {
                    mma16816(acc[mf][nf], ah, bh[nf]);
                    mma16816(acc[mf][nf], ah, blr[nf]);
                    mma16816(acc[mf][nf], al, bh[nf]);
                }
            }
        }
        __syncthreads();
    }

    // ---- epilogue: bias add, write xl1 / xr1 ----
    float* dst = (col0 < HID) ? g_xl1 : g_xr1;
    const float* bias = (col0 < HID) ? bl : br;
    int cbase = (col0 & (HID - 1)) + wc * 32;
#pragma unroll
    for (int mf = 0; mf < 4; mf++) {
        int r0 = row0 + wr * 64 + mf * 16 + qrow;
        int r1 = r0 + 8;
#pragma unroll
        for (int nf = 0; nf < 4; nf++) {
            int col = cbase + nf * 8 + qk;
            float b0 = bias[col], b1 = bias[col + 1];
            if (r0 < NN) {
                float2 v = { acc[mf][nf][0] + b0, acc[mf][nf][1] + b1 };
                *(float2*)(dst + (size_t)r0 * HID + col) = v;
            }
            if (r1 < NN) {
                float2 v = { acc[mf][nf][2] + b0, acc[mf][nf][3] + b1 };
                *(float2*)(dst + (size_t)r1 * HID + col) = v;
            }
        }
    }
}

// ============================ 4) CSR build ==================================
__global__ void k_count(const int* __restrict__ ei)
{
    int e = blockIdx.x * blockDim.x + threadIdx.x;
    if (e >= ETOT) return;
    int dst = (e < EIN) ? ei[EIN + e] : (e - EIN);
    atomicAdd(&g_deg[dst], 1);
}

__global__ __launch_bounds__(1024) void k_scan()
{
    const int CH = 10;
    int t = threadIdx.x;
    int base = t * CH;
    int local[CH]; int s = 0;
#pragma unroll
    for (int i = 0; i < CH; i++) {
        int idx = base + i;
        int v = (idx < NN) ? g_deg[idx] : 0;
        local[i] = s; s += v;
    }
    int lane = t & 31, wid = t >> 5;
    int inc = s;
#pragma unroll
    for (int o = 1; o < 32; o <<= 1) {
        int u = __shfl_up_sync(0xffffffffu, inc, o);
        if (lane >= o) inc += u;
    }
    __shared__ int wsum[32];
    if (lane == 31) wsum[wid] = inc;
    __syncthreads();
    if (wid == 0) {
        int v = wsum[lane];
#pragma unroll
        for (int o = 1; o < 32; o <<= 1) {
            int u = __shfl_up_sync(0xffffffffu, v, o);
            if (lane >= o) v += u;
        }
        wsum[lane] = v;
    }
    __syncthreads();
    int excl = inc - s + (wid > 0 ? wsum[wid - 1] : 0);
#pragma unroll
    for (int i = 0; i < CH; i++) {
        int idx = base + i;
        if (idx < NN) { g_rowptr[idx] = excl + local[i]; g_cursor[idx] = excl + local[i]; }
    }
    if (t == 1023) g_rowptr[NN] = excl + s;
}

__global__ void k_scatter(const int* __restrict__ ei)
{
    int e = blockIdx.x * blockDim.x + threadIdx.x;
    if (e >= ETOT) return;
    int src, dst;
    if (e < EIN) { src = ei[e]; dst = ei[EIN + e]; }
    else         { src = e - EIN; dst = src; }
    int pos = atomicAdd(&g_cursor[dst], 1);
    g_eidx[pos] = e;
    g_esrc[pos] = src;
}

// ============================ 5) edge logits L1 =============================
__global__ __launch_bounds__(256) void k_logits1(const int* __restrict__ ei,
                                                 const float* __restrict__ att)
{
    int w = (blockIdx.x * blockDim.x + threadIdx.x) >> 5;
    int lane = threadIdx.x & 31;
    if (w >= ETOT) return;
    int e = w;
    int src, dst;
    if (e < EIN) { src = ei[e]; dst = ei[EIN + e]; }
    else         { src = e - EIN; dst = src; }
    const float4* pl = (const float4*)(g_xl1 + src * HID);
    const float4* pr = (const float4*)(g_xr1 + dst * HID);
    const float4* pa = (const float4*)att;
#pragma unroll
    for (int h = 0; h < NH; h++) {
        float4 a = pl[h * 32 + lane];
        float4 b = pr[h * 32 + lane];
        float4 wv = pa[h * 32 + lane];
        float v0 = leaky(a.x + b.x, 0.2f);
        float v1 = leaky(a.y + b.y, 0.2f);
        float v2 = leaky(a.z + b.z, 0.2f);
        float v3 = leaky(a.w + b.w, 0.2f);
        float s = v0 * wv.x + v1 * wv.y + v2 * wv.z + v3 * wv.w;
#pragma unroll
        for (int o = 16; o; o >>= 1) s += __shfl_xor_sync(0xffffffffu, s, o);
        if (lane == 0) g_log1[e * NH + h] = s;
    }
}

// ============================ 6) segment softmax ============================
__global__ __launch_bounds__(256) void k_softmax(int which)
{
    float* logit = which ? g_log2 : g_log1;
    int n = (blockIdx.x * blockDim.x + threadIdx.x) >> 5;
    int lane = threadIdx.x & 31;
    if (n >= NN) return;
    int beg = g_rowptr[n], end = g_rowptr[n + 1];
    float m[NH];
#pragma unroll
    for (int h = 0; h < NH; h++) m[h] = -1e30f;
    for (int s = beg + lane; s < end; s += 32) {
        const float4* p = (const float4*)(logit + g_eidx[s] * NH);
        float4 a = p[0], b = p[1];
        m[0] = fmaxf(m[0], a.x); m[1] = fmaxf(m[1], a.y);
        m[2] = fmaxf(m[2], a.z); m[3] = fmaxf(m[3], a.w);
        m[4] = fmaxf(m[4], b.x); m[5] = fmaxf(m[5], b.y);
        m[6] = fmaxf(m[6], b.z); m[7] = fmaxf(m[7], b.w);
    }
#pragma unroll
    for (int h = 0; h < NH; h++)
#pragma unroll
        for (int o = 16; o; o >>= 1)
            m[h] = fmaxf(m[h], __shfl_xor_sync(0xffffffffu, m[h], o));
    float sum[NH];
#pragma unroll
    for (int h = 0; h < NH; h++) sum[h] = 0.f;
    for (int s = beg + lane; s < end; s += 32) {
        const float4* p = (const float4*)(logit + g_eidx[s] * NH);
        float4 a = p[0], b = p[1];
        sum[0] += __expf(a.x - m[0]); sum[1] += __expf(a.y - m[1]);
        sum[2] += __expf(a.z - m[2]); sum[3] += __expf(a.w - m[3]);
        sum[4] += __expf(b.x - m[4]); sum[5] += __expf(b.y - m[5]);
        sum[6] += __expf(b.z - m[6]); sum[7] += __expf(b.w - m[7]);
    }
#pragma unroll
    for (int h = 0; h < NH; h++) {
#pragma unroll
        for (int o = 16; o; o >>= 1)
            sum[h] += __shfl_xor_sync(0xffffffffu, sum[h], o);
        sum[h] = 1.f / (sum[h] + 1e-16f);
    }
    for (int s = beg + lane; s < end; s += 32) {
        float4* p = (float4*)(logit + g_eidx[s] * NH);
        float4 a = p[0], b = p[1];
        a.x = __expf(a.x - m[0]) * sum[0]; a.y = __expf(a.y - m[1]) * sum[1];
        a.z = __expf(a.z - m[2]) * sum[2]; a.w = __expf(a.w - m[3]) * sum[3];
        b.x = __expf(b.x - m[4]) * sum[4]; b.y = __expf(b.y - m[5]) * sum[5];
        b.z = __expf(b.z - m[6]) * sum[6]; b.w = __expf(b.w - m[7]) * sum[7];
        p[0] = a; p[1] = b;
    }
}

// ============================ 7) aggregation L1 =============================
__global__ __launch_bounds__(256) void k_agg1(const float* __restrict__ bias)
{
    int i = blockIdx.x;
    int t = threadIdx.x;
    int c0 = t * 4;
    int h = c0 >> 7;
    int beg = g_rowptr[i], end = g_rowptr[i + 1];
    float4 acc = {0.f, 0.f, 0.f, 0.f};
    for (int s = beg; s < end; s++) {
        int e = g_eidx[s];
        int src = g_esrc[s];
        float al = g_log1[e * NH + h];
        float4 v = *(const float4*)(g_xl1 + src * HID + c0);
        acc.x += al * v.x; acc.y += al * v.y;
        acc.z += al * v.z; acc.w += al * v.w;
    }
    float4 b = *(const float4*)(bias + c0);
    acc.x += b.x; acc.y += b.y; acc.z += b.z; acc.w += b.w;
    *(float4*)(g_h1 + i * HID + c0) = acc;
}

// ============================ 8) BN2 stats ==================================
__global__ __launch_bounds__(256) void k_bn2_stats()
{
    int r0 = blockIdx.x * 128;
    int t = threadIdx.x;
    float s[4] = {0,0,0,0}, q[4] = {0,0,0,0};
    int rmax = min(128, NN - r0);
    for (int r = 0; r < rmax; r++) {
        const float* row = g_h1 + (r0 + r) * HID;
#pragma unroll
        for (int j = 0; j < 4; j++) {
            float v = row[t + j * 256];
            s[j] += v; q[j] += v * v;
        }
    }
#pragma unroll
    for (int j = 0; j < 4; j++) {
        atomicAdd(&g_stat2[t + j * 256], s[j]);
        atomicAdd(&g_stat2[HID + t + j * 256], q[j]);
    }
}

// ============================ 9) BN2 norm + leaky(0.01) =====================
__global__ void k_bn2_norm(const float* __restrict__ gamma,
                           const float* __restrict__ beta)
{
    int i4 = blockIdx.x * blockDim.x + threadIdx.x;
    if (i4 >= NN * HID / 4) return;
    int c4 = i4 & (HID / 4 - 1);
    float4 v = ((const float4*)g_h1)[i4];
    float4 su = ((const float4*)g_stat2)[c4];
    float4 sq = ((const float4*)(g_stat2 + HID))[c4];
    float4 gm = ((const float4*)gamma)[c4];
    float4 bt = ((const float4*)beta)[c4];
    float mu, var, rs, o;
    float4 r;
    mu = su.x * (1.f/NN); var = sq.x * (1.f/NN) - mu*mu; rs = rsqrtf(var + 1e-5f);
    o = (v.x - mu) * rs * gm.x + bt.x; r.x = leaky(o, 0.01f);
    mu = su.y * (1.f/NN); var = sq.y * (1.f/NN) - mu*mu; rs = rsqrtf(var + 1e-5f);
    o = (v.y - mu) * rs * gm.y + bt.y; r.y = leaky(o, 0.01f);
    mu = su.z * (1.f/NN); var = sq.z * (1.f/NN) - mu*mu; rs = rsqrtf(var + 1e-5f);
    o = (v.z - mu) * rs * gm.z + bt.z; r.z = leaky(o, 0.01f);
    mu = su.w * (1.f/NN); var = sq.w * (1.f/NN) - mu*mu; rs = rsqrtf(var + 1e-5f);
    o = (v.w - mu) * rs * gm.w + bt.w; r.w = leaky(o, 0.01f);
    ((float4*)g_h2)[i4] = r;
}

// ============================ 10) GEMM2 (tall-skinny) =======================
__global__ __launch_bounds__(256) void k_gemm2(const float* __restrict__ Wl,
                                               const float* __restrict__ bl,
                                               const float* __restrict__ Wr,
                                               const float* __restrict__ br)
{
    int rw = (blockIdx.x * blockDim.x + threadIdx.x) >> 5;
    int lane = threadIdx.x & 31;
    if (rw >= NN) return;
    const float* row = g_h2 + rw * HID;
    float acc[16];
#pragma unroll
    for (int j = 0; j < 16; j++) acc[j] = 0.f;
    for (int k = lane; k < HID; k += 32) {
        float a = row[k];
        float4 w0 = ((const float4*)(Wl + k * 8))[0];
        float4 w1 = ((const float4*)(Wl + k * 8))[1];
        float4 u0 = ((const float4*)(Wr + k * 8))[0];
        float4 u1 = ((const float4*)(Wr + k * 8))[1];
        acc[0] += a*w0.x; acc[1] += a*w0.y; acc[2] += a*w0.z; acc[3] += a*w0.w;
        acc[4] += a*w1.x; acc[5] += a*w1.y; acc[6] += a*w1.z; acc[7] += a*w1.w;
        acc[8] += a*u0.x; acc[9] += a*u0.y; acc[10]+= a*u0.z; acc[11]+= a*u0.w;
        acc[12]+= a*u1.x; acc[13]+= a*u1.y; acc[14]+= a*u1.z; acc[15]+= a*u1.w;
    }
#pragma unroll
    for (int j = 0; j < 16; j++)
#pragma unroll
        for (int o = 16; o; o >>= 1)
            acc[j] += __shfl_xor_sync(0xffffffffu, acc[j], o);
    if (lane < 8)       g_xl2[rw * 8 + lane]       = acc[lane] + bl[lane];
    else if (lane < 16) g_xr2[rw * 8 + (lane - 8)] = acc[lane] + br[lane - 8];
}

// ============================ 11) edge logits L2 ============================
__global__ void k_logits2(const int* __restrict__ ei,
                          const float* __restrict__ att)
{
    int e = blockIdx.x * blockDim.x + threadIdx.x;
    if (e >= ETOT) return;
    int src, dst;
    if (e < EIN) { src = ei[e]; dst = ei[EIN + e]; }
    else         { src = e - EIN; dst = src; }
    float4 l0 = ((const float4*)(g_xl2 + src * 8))[0];
    float4 l1 = ((const float4*)(g_xl2 + src * 8))[1];
    float4 r0 = ((const float4*)(g_xr2 + dst * 8))[0];
    float4 r1 = ((const float4*)(g_xr2 + dst * 8))[1];
    float4 a0 = ((const float4*)att)[0];
    float4 a1 = ((const float4*)att)[1];
    float4 o0, o1;
    o0.x = leaky(l0.x + r0.x, 0.2f) * a0.x;
    o0.y = leaky(l0.y + r0.y, 0.2f) * a0.y;
    o0.z = leaky(l0.z + r0.z, 0.2f) * a0.z;
    o0.w = leaky(l0.w + r0.w, 0.2f) * a0.w;
    o1.x = leaky(l1.x + r1.x, 0.2f) * a1.x;
    o1.y = leaky(l1.y + r1.y, 0.2f) * a1.y;
    o1.z = leaky(l1.z + r1.z, 0.2f) * a1.z;
    o1.w = leaky(l1.w + r1.w, 0.2f) * a1.w;
    ((float4*)(g_log2 + e * 8))[0] = o0;
    ((float4*)(g_log2 + e * 8))[1] = o1;
}

// ============================ 12) aggregation L2 + head mean ================
__global__ void k_agg2(const float* __restrict__ bias2, float* __restrict__ out)
{
    int i = blockIdx.x * blockDim.x + threadIdx.x;
    if (i >= NN) return;
    int beg = g_rowptr[i], end = g_rowptr[i + 1];
    float a0 = 0, a1 = 0, a2 = 0, a3 = 0, a4 = 0, a5 = 0, a6 = 0, a7 = 0;
    for (int s = beg; s < end; s++) {
        int e = g_eidx[s];
        int src = g_esrc[s];
        float4 p0 = ((const float4*)(g_log2 + e * 8))[0];
        float4 p1 = ((const float4*)(g_log2 + e * 8))[1];
        float4 v0 = ((const float4*)(g_xl2 + src * 8))[0];
        float4 v1 = ((const float4*)(g_xl2 + src * 8))[1];
        a0 += p0.x * v0.x; a1 += p0.y * v0.y; a2 += p0.z * v0.z; a3 += p0.w * v0.w;
        a4 += p1.x * v1.x; a5 += p1.y * v1.y; a6 += p1.z * v1.z; a7 += p1.w * v1.w;
    }
    float s8 = (a0 + a1 + a2 + a3 + a4 + a5 + a6 + a7) * 0.125f;
    out[i] = s8 + bias2[0];
}

// ============================ launch ========================================
extern "C" void kernel_launch(void* const* d_in, const int* in_sizes, int n_in,
                              void* d_out, int out_size)
{
    const float* x      = (const float*)d_in[0];
    const float* gamma1 = (const float*)d_in[1];
    const float* beta1  = (const float*)d_in[2];
    const float* Wl1    = (const float*)d_in[3];
    const float* bl1    = (const float*)d_in[4];
    const float* Wr1    = (const float*)d_in[5];
    const float* br1    = (const float*)d_in[6];
    const float* att1   = (const float*)d_in[7];
    const float* bias1  = (const float*)d_in[8];
    const float* gamma2 = (const float*)d_in[9];
    const float* beta2  = (const float*)d_in[10];
    const float* Wl2    = (const float*)d_in[11];
    const float* bl2    = (const float*)d_in[12];
    const float* Wr2    = (const float*)d_in[13];
    const float* br2    = (const float*)d_in[14];
    const float* att2   = (const float*)d_in[15];
    const float* bias2  = (const float*)d_in[16];
    const int*   ei     = (const int*)  d_in[17];
    float* out = (float*)d_out;

    k_zero<<<(NN + 255) / 256, 256>>>();
    k_bn1_stats<<<DIN, 256>>>(x);
    k_wsplit<<<(2048 * KPAD + 255) / 256, 256>>>(Wl1, Wr1);
    k_bn1_split<<<(NPAD * KPAD + 255) / 256, 256>>>(x, gamma1, beta1);
    k_gemm1_mma<<<dim3(16, NPAD / 128), 256>>>(bl1, br1);

    k_count<<<(ETOT + 255) / 256, 256>>>(ei);
    k_scan<<<1, 1024>>>();
    k_scatter<<<(ETOT + 255) / 256, 256>>>(ei);

    k_logits1<<<(ETOT * 32 + 255) / 256, 256>>>(ei, att1);
    k_softmax<<<(NN * 32 + 255) / 256, 256>>>(0);
    k_agg1<<<NN, 256>>>(bias1);

    k_bn2_stats<<<(NN + 127) / 128, 256>>>();
    k_bn2_norm<<<(NN * HID / 4 + 255) / 256, 256>>>(gamma2, beta2);

    k_gemm2<<<(NN * 32 + 255) / 256, 256>>>(Wl2, bl2, Wr2, br2);
    k_logits2<<<(ETOT + 255) / 256, 256>>>(ei, att2);
    k_softmax<<<(NN * 32 + 255) / 256, 256>>>(1);
    k_agg2<<<(NN + 255) / 256, 256>>>(bias2, out);
}

// round 12
// speedup vs baseline: 1.3370x; 1.0010x over previous
#include <cuda_runtime.h>
#include <cuda_bf16.h>
#include <cstdint>

// ---------------------------------------------------------------------------
// GATv2 x2 + BatchNorm GNN, GB300 (sm_103a).
// GEMM1 via mma.sync bf16 2-way split. Edge phase: CSR warp-per-node with
// online (max,sum) softmax fused into the logits pass; alpha computed inline
// in aggregation.
// ---------------------------------------------------------------------------

#define NN     10000     // nodes
#define NPAD   10112     // 79 * 128
#define EIN    160000    // input edges
#define ETOT   170000    // + self loops
#define DIN    165
#define KPAD   192       // DIN padded to 6 chunks of 32
#define HID    1024
#define NH     8

// ----------------------------- scratch (no allocs allowed) -----------------
__device__ __nv_bfloat16 g_a_hi[NPAD * KPAD];   // BN1(x) split hi   [row][k]
__device__ __nv_bfloat16 g_a_lo[NPAD * KPAD];   // BN1(x) split lo
__device__ __nv_bfloat16 g_w_hi[2048 * KPAD];   // [Wl1|Wr1]^T hi    [n][k]
__device__ __nv_bfloat16 g_w_lo[2048 * KPAD];
__device__ float g_stat1[2 * DIN];
__device__ float g_xl1 [NN * HID];
__device__ float g_xr1 [NN * HID];
__device__ float g_log1[ETOT * NH];             // raw logits L1
__device__ float g_ms1 [NN * 16];               // per node: m[8], s[8]
__device__ float g_h1  [NN * HID];
__device__ float g_stat2[2 * HID];
__device__ float g_h2  [NN * HID];
__device__ float g_xl2 [NN * NH];
__device__ float g_xr2 [NN * NH];
__device__ float g_log2[ETOT * NH];             // raw logits L2
__device__ float g_ms2 [NN * 16];
__device__ int   g_deg   [NN];
__device__ int   g_rowptr[NN + 1];
__device__ int   g_cursor[NN];
__device__ int   g_eidx  [ETOT];
__device__ int   g_esrc  [ETOT];

__device__ __forceinline__ float leaky(float v, float s) { return v > 0.f ? v : s * v; }

// ============================ 0) zero scratch ===============================
__global__ void k_zero()
{
    int i = blockIdx.x * blockDim.x + threadIdx.x;
    if (i < 2 * HID) g_stat2[i] = 0.f;
    if (i < NN)      g_deg[i] = 0;
}

// ============================ 1) BN1 stats ==================================
__global__ __launch_bounds__(256) void k_bn1_stats(const float* __restrict__ x)
{
    int c = blockIdx.x, t = threadIdx.x;
    float s = 0.f, q = 0.f;
    for (int r = t; r < NN; r += 256) {
        float v = x[r * DIN + c];
        s += v; q += v * v;
    }
    __shared__ float ss[256], qq[256];
    ss[t] = s; qq[t] = q; __syncthreads();
    for (int o = 128; o; o >>= 1) {
        if (t < o) { ss[t] += ss[t + o]; qq[t] += qq[t + o]; }
        __syncthreads();
    }
    if (t == 0) { g_stat1[c] = ss[0]; g_stat1[DIN + c] = qq[0]; }
}

// ============================ 2) BN1 normalize + bf16 split =================
__global__ void k_bn1_split(const float* __restrict__ x,
                            const float* __restrict__ gamma,
                            const float* __restrict__ beta)
{
    int idx = blockIdx.x * blockDim.x + threadIdx.x;
    if (idx >= NPAD * KPAD) return;
    int r = idx / KPAD;
    int k = idx - r * KPAD;
    float val = 0.f;
    if (r < NN && k < DIN) {
        float mu  = g_stat1[k] * (1.f / NN);
        float var = g_stat1[DIN + k] * (1.f / NN) - mu * mu;
        float rs  = rsqrtf(var + 1e-5f);
        val = (x[r * DIN + k] - mu) * rs * gamma[k] + beta[k];
    }
    __nv_bfloat16 hi = __float2bfloat16(val);
    __nv_bfloat16 lo = __float2bfloat16(val - __bfloat162float(hi));
    g_a_hi[idx] = hi;
    g_a_lo[idx] = lo;
}

// ============================ 2b) W transpose + split =======================
__global__ void k_wsplit(const float* __restrict__ Wl, const float* __restrict__ Wr)
{
    int idx = blockIdx.x * blockDim.x + threadIdx.x;
    if (idx >= 2048 * KPAD) return;
    int n = idx / KPAD;
    int k = idx - n * KPAD;
    float val = 0.f;
    if (k < DIN)
        val = (n < HID) ? Wl[k * HID + n] : Wr[k * HID + (n - HID)];
    __nv_bfloat16 hi = __float2bfloat16(val);
    __nv_bfloat16 lo = __float2bfloat16(val - __bfloat162float(hi));
    g_w_hi[idx] = hi;
    g_w_lo[idx] = lo;
}

// ============================ 3) GEMM1 via mma.sync =========================
#define GSTRIDE 40

__device__ __forceinline__ void mma16816(float* c, const uint32_t* a, const uint32_t* b)
{
    asm volatile(
        "mma.sync.aligned.m16n8k16.row.col.f32.bf16.bf16.f32 "
        "{%0,%1,%2,%3}, {%4,%5,%6,%7}, {%8,%9}, {%0,%1,%2,%3};"
        : "+f"(c[0]), "+f"(c[1]), "+f"(c[2]), "+f"(c[3])
        : "r"(a[0]), "r"(a[1]), "r"(a[2]), "r"(a[3]), "r"(b[0]), "r"(b[1]));
}

__global__ __launch_bounds__(256) void k_gemm1_mma(const float* __restrict__ bl,
                                                   const float* __restrict__ br)
{
    __shared__ __align__(16) __nv_bfloat16 sAh[128 * GSTRIDE];
    __shared__ __align__(16) __nv_bfloat16 sAl[128 * GSTRIDE];
    __shared__ __align__(16) __nv_bfloat16 sBh[128 * GSTRIDE];
    __shared__ __align__(16) __nv_bfloat16 sBl[128 * GSTRIDE];

    int tid = threadIdx.x;
    int wid = tid >> 5, lane = tid & 31;
    int wr = wid & 1, wc = wid >> 1;
    int qrow = lane >> 2;
    int qk   = (lane & 3) * 2;
    int row0 = blockIdx.y * 128;
    int col0 = blockIdx.x * 128;

    float acc[4][4][4];
#pragma unroll
    for (int mf = 0; mf < 4; mf++)
#pragma unroll
        for (int nf = 0; nf < 4; nf++)
#pragma unroll
            for (int j = 0; j < 4; j++) acc[mf][nf][j] = 0.f;

    const __nv_bfloat16* pAh = g_a_hi + (size_t)row0 * KPAD;
    const __nv_bfloat16* pAl = g_a_lo + (size_t)row0 * KPAD;
    const __nv_bfloat16* pBh = g_w_hi + (size_t)col0 * KPAD;
    const __nv_bfloat16* pBl = g_w_lo + (size_t)col0 * KPAD;

    for (int c = 0; c < 6; c++) {
#pragma unroll
        for (int i = 0; i < 2; i++) {
            int flat = i * 256 + tid;
            int row = flat >> 2, q = flat & 3;
            size_t go = (size_t)row * KPAD + c * 32 + q * 8;
            int so = row * GSTRIDE + q * 8;
            *(uint4*)(sAh + so) = *(const uint4*)(pAh + go);
            *(uint4*)(sAl + so) = *(const uint4*)(pAl + go);
            *(uint4*)(sBh + so) = *(const uint4*)(pBh + go);
            *(uint4*)(sBl + so) = *(const uint4*)(pBl + go);
        }
        __syncthreads();

#pragma unroll
        for (int ks = 0; ks < 32; ks += 16) {
            uint32_t bh[4][2], blr[4][2];
#pragma unroll
            for (int nf = 0; nf < 4; nf++) {
                int n = wc * 32 + nf * 8 + qrow;
                const __nv_bfloat16* bp = sBh + n * GSTRIDE + ks + qk;
                const __nv_bfloat16* lp = sBl + n * GSTRIDE + ks + qk;
                bh[nf][0]  = *(const uint32_t*)bp;
                bh[nf][1]  = *(const uint32_t*)(bp + 8);
                blr[nf][0] = *(const uint32_t*)lp;
                blr[nf][1] = *(const uint32_t*)(lp + 8);
            }
#pragma unroll
            for (int mf = 0; mf < 4; mf++) {
                int m = wr * 64 + mf * 16 + qrow;
                const __nv_bfloat16* ap = sAh + m * GSTRIDE + ks + qk;
                const __nv_bfloat16* lp = sAl + m * GSTRIDE + ks + qk;
                uint32_t ah[4], al[4];
                ah[0] = *(const uint32_t*)ap;
                ah[1] = *(const uint32_t*)(ap + 8 * GSTRIDE);
                ah[2] = *(const uint32_t*)(ap + 8);
                ah[3] = *(const uint32_t*)(ap + 8 * GSTRIDE + 8);
                al[0] = *(const uint32_t*)lp;
                al[1] = *(const uint32_t*)(lp + 8 * GSTRIDE);
                al[2] = *(const uint32_t*)(lp + 8);
                al[3] = *(const uint32_t*)(lp + 8 * GSTRIDE + 8);
#pragma unroll
                for (int nf = 0; nf < 4; nf++) {
                    mma16816(acc[mf][nf], ah, bh[nf]);
                    mma16816(acc[mf][nf], ah, blr[nf]);
                    mma16816(acc[mf][nf], al, bh[nf]);
                }
            }
        }
        __syncthreads();
    }

    float* dst = (col0 < HID) ? g_xl1 : g_xr1;
    const float* bias = (col0 < HID) ? bl : br;
    int cbase = (col0 & (HID - 1)) + wc * 32;
#pragma unroll
    for (int mf = 0; mf < 4; mf++) {
        int r0 = row0 + wr * 64 + mf * 16 + qrow;
        int r1 = r0 + 8;
#pragma unroll
        for (int nf = 0; nf < 4; nf++) {
            int col = cbase + nf * 8 + qk;
            float b0 = bias[col], b1 = bias[col + 1];
            if (r0 < NN) {
                float2 v = { acc[mf][nf][0] + b0, acc[mf][nf][1] + b1 };
                *(float2*)(dst + (size_t)r0 * HID + col) = v;
            }
            if (r1 < NN) {
                float2 v = { acc[mf][nf][2] + b0, acc[mf][nf][3] + b1 };
                *(float2*)(dst + (size_t)r1 * HID + col) = v;
            }
        }
    }
}

// ============================ 4) CSR build ==================================
__global__ void k_count(const int* __restrict__ ei)
{
    int e = blockIdx.x * blockDim.x + threadIdx.x;
    if (e >= ETOT) return;
    int dst = (e < EIN) ? ei[EIN + e] : (e - EIN);
    atomicAdd(&g_deg[dst], 1);
}

__global__ __launch_bounds__(1024) void k_scan()
{
    const int CH = 10;
    int t = threadIdx.x;
    int base = t * CH;
    int local[CH]; int s = 0;
#pragma unroll
    for (int i = 0; i < CH; i++) {
        int idx = base + i;
        int v = (idx < NN) ? g_deg[idx] : 0;
        local[i] = s; s += v;
    }
    int lane = t & 31, wid = t >> 5;
    int inc = s;
#pragma unroll
    for (int o = 1; o < 32; o <<= 1) {
        int u = __shfl_up_sync(0xffffffffu, inc, o);
        if (lane >= o) inc += u;
    }
    __shared__ int wsum[32];
    if (lane == 31) wsum[wid] = inc;
    __syncthreads();
    if (wid == 0) {
        int v = wsum[lane];
#pragma unroll
        for (int o = 1; o < 32; o <<= 1) {
            int u = __shfl_up_sync(0xffffffffu, v, o);
            if (lane >= o) v += u;
        }
        wsum[lane] = v;
    }
    __syncthreads();
    int excl = inc - s + (wid > 0 ? wsum[wid - 1] : 0);
#pragma unroll
    for (int i = 0; i < CH; i++) {
        int idx = base + i;
        if (idx < NN) { g_rowptr[idx] = excl + local[i]; g_cursor[idx] = excl + local[i]; }
    }
    if (t == 1023) g_rowptr[NN] = excl + s;
}

__global__ void k_scatter(const int* __restrict__ ei)
{
    int e = blockIdx.x * blockDim.x + threadIdx.x;
    if (e >= ETOT) return;
    int src, dst;
    if (e < EIN) { src = ei[e]; dst = ei[EIN + e]; }
    else         { src = e - EIN; dst = src; }
    int pos = atomicAdd(&g_cursor[dst], 1);
    g_eidx[pos] = e;
    g_esrc[pos] = src;
}

// ============================ 5) L1 logits + online softmax stats ===========
// one warp per node; xr row cached in registers; logits stored raw; per-node
// per-head running (max, sum) stored to g_ms1.
__global__ __launch_bounds__(256) void k_edge1(const float* __restrict__ att)
{
    int n = (blockIdx.x * blockDim.x + threadIdx.x) >> 5;
    int lane = threadIdx.x & 31;
    if (n >= NN) return;

    const float4* pa = (const float4*)att;
    const float4* pr = (const float4*)(g_xr1 + (size_t)n * HID);
    float4 attv[NH], xrv[NH];
#pragma unroll
    for (int h = 0; h < NH; h++) {
        attv[h] = pa[h * 32 + lane];
        xrv[h]  = pr[h * 32 + lane];
    }

    float m[NH], s[NH];
#pragma unroll
    for (int h = 0; h < NH; h++) { m[h] = -1e30f; s[h] = 0.f; }

    int beg = g_rowptr[n], end = g_rowptr[n + 1];
    for (int slot = beg; slot < end; slot++) {
        int src = g_esrc[slot];
        int e   = g_eidx[slot];
        const float4* pl = (const float4*)(g_xl1 + (size_t)src * HID);
        float4 xlv[NH];
#pragma unroll
        for (int h = 0; h < NH; h++) xlv[h] = pl[h * 32 + lane];

        float lg[NH];
#pragma unroll
        for (int h = 0; h < NH; h++) {
            float v0 = leaky(xlv[h].x + xrv[h].x, 0.2f);
            float v1 = leaky(xlv[h].y + xrv[h].y, 0.2f);
            float v2 = leaky(xlv[h].z + xrv[h].z, 0.2f);
            float v3 = leaky(xlv[h].w + xrv[h].w, 0.2f);
            float p = v0 * attv[h].x + v1 * attv[h].y + v2 * attv[h].z + v3 * attv[h].w;
#pragma unroll
            for (int o = 16; o; o >>= 1) p += __shfl_xor_sync(0xffffffffu, p, o);
            lg[h] = p;
            // online (m, s)
            float nm = fmaxf(m[h], p);
            s[h] = s[h] * __expf(m[h] - nm) + __expf(p - nm);
            m[h] = nm;
        }
        if (lane == 0) {
            float4 L0 = { lg[0], lg[1], lg[2], lg[3] };
            float4 L1 = { lg[4], lg[5], lg[6], lg[7] };
            ((float4*)(g_log1 + (size_t)e * NH))[0] = L0;
            ((float4*)(g_log1 + (size_t)e * NH))[1] = L1;
        }
    }
    if (lane == 0) {
        float4 M0 = { m[0], m[1], m[2], m[3] };
        float4 M1 = { m[4], m[5], m[6], m[7] };
        float4 S0 = { s[0], s[1], s[2], s[3] };
        float4 S1 = { s[4], s[5], s[6], s[7] };
        float4* pm = (float4*)(g_ms1 + n * 16);
        pm[0] = M0; pm[1] = M1; pm[2] = S0; pm[3] = S1;
    }
}

// ============================ 6) aggregation L1 (alpha inline) ==============
__global__ __launch_bounds__(256) void k_agg1(const float* __restrict__ bias)
{
    int i = blockIdx.x;
    int t = threadIdx.x;
    int c0 = t * 4;
    int h = c0 >> 7;                           // uniform per warp
    float m    = g_ms1[i * 16 + h];
    float is   = 1.f / (g_ms1[i * 16 + 8 + h] + 1e-16f);
    int beg = g_rowptr[i], end = g_rowptr[i + 1];
    float4 acc = {0.f, 0.f, 0.f, 0.f};
    for (int s = beg; s < end; s++) {
        int e = g_eidx[s];
        int src = g_esrc[s];
        float al = __expf(g_log1[(size_t)e * NH + h] - m) * is;
        float4 v = *(const float4*)(g_xl1 + (size_t)src * HID + c0);
        acc.x += al * v.x; acc.y += al * v.y;
        acc.z += al * v.z; acc.w += al * v.w;
    }
    float4 b = *(const float4*)(bias + c0);
    acc.x += b.x; acc.y += b.y; acc.z += b.z; acc.w += b.w;
    *(float4*)(g_h1 + (size_t)i * HID + c0) = acc;
}

// ============================ 8) BN2 stats ==================================
__global__ __launch_bounds__(256) void k_bn2_stats()
{
    int r0 = blockIdx.x * 128;
    int t = threadIdx.x;
    float s[4] = {0,0,0,0}, q[4] = {0,0,0,0};
    int rmax = min(128, NN - r0);
    for (int r = 0; r < rmax; r++) {
        const float* row = g_h1 + (size_t)(r0 + r) * HID;
#pragma unroll
        for (int j = 0; j < 4; j++) {
            float v = row[t + j * 256];
            s[j] += v; q[j] += v * v;
        }
    }
#pragma unroll
    for (int j = 0; j < 4; j++) {
        atomicAdd(&g_stat2[t + j * 256], s[j]);
        atomicAdd(&g_stat2[HID + t + j * 256], q[j]);
    }
}

// ============================ 9) BN2 norm + leaky(0.01) =====================
__global__ void k_bn2_norm(const float* __restrict__ gamma,
                           const float* __restrict__ beta)
{
    int i4 = blockIdx.x * blockDim.x + threadIdx.x;
    if (i4 >= NN * HID / 4) return;
    int c4 = i4 & (HID / 4 - 1);
    float4 v = ((const float4*)g_h1)[i4];
    float4 su = ((const float4*)g_stat2)[c4];
    float4 sq = ((const float4*)(g_stat2 + HID))[c4];
    float4 gm = ((const float4*)gamma)[c4];
    float4 bt = ((const float4*)beta)[c4];
    float mu, var, rs, o;
    float4 r;
    mu = su.x * (1.f/NN); var = sq.x * (1.f/NN) - mu*mu; rs = rsqrtf(var + 1e-5f);
    o = (v.x - mu) * rs * gm.x + bt.x; r.x = leaky(o, 0.01f);
    mu = su.y * (1.f/NN); var = sq.y * (1.f/NN) - mu*mu; rs = rsqrtf(var + 1e-5f);
    o = (v.y - mu) * rs * gm.y + bt.y; r.y = leaky(o, 0.01f);
    mu = su.z * (1.f/NN); var = sq.z * (1.f/NN) - mu*mu; rs = rsqrtf(var + 1e-5f);
    o = (v.z - mu) * rs * gm.z + bt.z; r.z = leaky(o, 0.01f);
    mu = su.w * (1.f/NN); var = sq.w * (1.f/NN) - mu*mu; rs = rsqrtf(var + 1e-5f);
    o = (v.w - mu) * rs * gm.w + bt.w; r.w = leaky(o, 0.01f);
    ((float4*)g_h2)[i4] = r;
}

// ============================ 10) GEMM2 (tall-skinny) =======================
__global__ __launch_bounds__(256) void k_gemm2(const float* __restrict__ Wl,
                                               const float* __restrict__ bl,
                                               const float* __restrict__ Wr,
                                               const float* __restrict__ br)
{
    int rw = (blockIdx.x * blockDim.x + threadIdx.x) >> 5;
    int lane = threadIdx.x & 31;
    if (rw >= NN) return;
    const float* row = g_h2 + (size_t)rw * HID;
    float acc[16];
#pragma unroll
    for (int j = 0; j < 16; j++) acc[j] = 0.f;
    for (int k = lane; k < HID; k += 32) {
        float a = row[k];
        float4 w0 = ((const float4*)(Wl + k * 8))[0];
        float4 w1 = ((const float4*)(Wl + k * 8))[1];
        float4 u0 = ((const float4*)(Wr + k * 8))[0];
        float4 u1 = ((const float4*)(Wr + k * 8))[1];
        acc[0] += a*w0.x; acc[1] += a*w0.y; acc[2] += a*w0.z; acc[3] += a*w0.w;
        acc[4] += a*w1.x; acc[5] += a*w1.y; acc[6] += a*w1.z; acc[7] += a*w1.w;
        acc[8] += a*u0.x; acc[9] += a*u0.y; acc[10]+= a*u0.z; acc[11]+= a*u0.w;
        acc[12]+= a*u1.x; acc[13]+= a*u1.y; acc[14]+= a*u1.z; acc[15]+= a*u1.w;
    }
#pragma unroll
    for (int j = 0; j < 16; j++)
#pragma unroll
        for (int o = 16; o; o >>= 1)
            acc[j] += __shfl_xor_sync(0xffffffffu, acc[j], o);
    if (lane < 8)       g_xl2[rw * 8 + lane]       = acc[lane] + bl[lane];
    else if (lane < 16) g_xr2[rw * 8 + (lane - 8)] = acc[lane] + br[lane - 8];
}

// ============================ 11) L2 logits + online stats ==================
// one warp per node; lanes 0..7 = heads (no shuffles needed).
__global__ __launch_bounds__(256) void k_edge2(const float* __restrict__ att)
{
    int n = (blockIdx.x * blockDim.x + threadIdx.x) >> 5;
    int lane = threadIdx.x & 31;
    if (n >= NN) return;
    bool act = lane < NH;
    float a  = act ? att[lane] : 0.f;
    float xr = act ? g_xr2[n * NH + lane] : 0.f;
    float m = -1e30f, s = 0.f;
    int beg = g_rowptr[n], end = g_rowptr[n + 1];
    for (int slot = beg; slot < end; slot++) {
        int src = g_esrc[slot];
        int e   = g_eidx[slot];
        if (act) {
            float xl = g_xl2[src * NH + lane];
            float lg = leaky(xl + xr, 0.2f) * a;
            g_log2[(size_t)e * NH + lane] = lg;
            float nm = fmaxf(m, lg);
            s = s * __expf(m - nm) + __expf(lg - nm);
            m = nm;
        }
    }
    if (act) {
        g_ms2[n * 16 + lane]     = m;
        g_ms2[n * 16 + 8 + lane] = s;
    }
}

// ============================ 12) aggregation L2 + head mean ================
__global__ void k_agg2(const float* __restrict__ bias2, float* __restrict__ out)
{
    int i = blockIdx.x * blockDim.x + threadIdx.x;
    if (i >= NN) return;
    float4 M0 = ((const float4*)(g_ms2 + i * 16))[0];
    float4 M1 = ((const float4*)(g_ms2 + i * 16))[1];
    float4 S0 = ((const float4*)(g_ms2 + i * 16))[2];
    float4 S1 = ((const float4*)(g_ms2 + i * 16))[3];
    float is0 = 1.f / (S0.x + 1e-16f), is1 = 1.f / (S0.y + 1e-16f);
    float is2 = 1.f / (S0.z + 1e-16f), is3 = 1.f / (S0.w + 1e-16f);
    float is4 = 1.f / (S1.x + 1e-16f), is5 = 1.f / (S1.y + 1e-16f);
    float is6 = 1.f / (S1.z + 1e-16f), is7 = 1.f / (S1.w + 1e-16f);
    int beg = g_rowptr[i], end = g_rowptr[i + 1];
    float a0 = 0, a1 = 0, a2 = 0, a3 = 0, a4 = 0, a5 = 0, a6 = 0, a7 = 0;
    for (int s = beg; s < end; s++) {
        int e = g_eidx[s];
        int src = g_esrc[s];
        float4 p0 = ((const float4*)(g_log2 + (size_t)e * NH))[0];
        float4 p1 = ((const float4*)(g_log2 + (size_t)e * NH))[1];
        float4 v0 = ((const float4*)(g_xl2 + src * NH))[0];
        float4 v1 = ((const float4*)(g_xl2 + src * NH))[1];
        a0 += __expf(p0.x - M0.x) * is0 * v0.x;
        a1 += __expf(p0.y - M0.y) * is1 * v0.y;
        a2 += __expf(p0.z - M0.z) * is2 * v0.z;
        a3 += __expf(p0.w - M0.w) * is3 * v0.w;
        a4 += __expf(p1.x - M1.x) * is4 * v1.x;
        a5 += __expf(p1.y - M1.y) * is5 * v1.y;
        a6 += __expf(p1.z - M1.z) * is6 * v1.z;
        a7 += __expf(p1.w - M1.w) * is7 * v1.w;
    }
    float s8 = (a0 + a1 + a2 + a3 + a4 + a5 + a6 + a7) * 0.125f;
    out[i] = s8 + bias2[0];
}

// ============================ launch ========================================
extern "C" void kernel_launch(void* const* d_in, const int* in_sizes, int n_in,
                              void* d_out, int out_size)
{
    const float* x      = (const float*)d_in[0];
    const float* gamma1 = (const float*)d_in[1];
    const float* beta1  = (const float*)d_in[2];
    const float* Wl1    = (const float*)d_in[3];
    const float* bl1    = (const float*)d_in[4];
    const float* Wr1    = (const float*)d_in[5];
    const float* br1    = (const float*)d_in[6];
    const float* att1   = (const float*)d_in[7];
    const float* bias1  = (const float*)d_in[8];
    const float* gamma2 = (const float*)d_in[9];
    const float* beta2  = (const float*)d_in[10];
    const float* Wl2    = (const float*)d_in[11];
    const float* bl2    = (const float*)d_in[12];
    const float* Wr2    = (const float*)d_in[13];
    const float* br2    = (const float*)d_in[14];
    const float* att2   = (const float*)d_in[15];
    const float* bias2  = (const float*)d_in[16];
    const int*   ei     = (const int*)  d_in[17];
    float* out = (float*)d_out;

    k_zero<<<(NN + 255) / 256, 256>>>();
    k_bn1_stats<<<DIN, 256>>>(x);
    k_wsplit<<<(2048 * KPAD + 255) / 256, 256>>>(Wl1, Wr1);
    k_bn1_split<<<(NPAD * KPAD + 255) / 256, 256>>>(x, gamma1, beta1);

    k_count<<<(ETOT + 255) / 256, 256>>>(ei);
    k_scan<<<1, 1024>>>();
    k_scatter<<<(ETOT + 255) / 256, 256>>>(ei);

    k_gemm1_mma<<<dim3(16, NPAD / 128), 256>>>(bl1, br1);

    k_edge1<<<(NN * 32 + 255) / 256, 256>>>(att1);
    k_agg1<<<NN, 256>>>(bias1);

    k_bn2_stats<<<(NN + 127) / 128, 256>>>();
    k_bn2_norm<<<(NN * HID / 4 + 255) / 256, 256>>>(gamma2, beta2);

    k_gemm2<<<(NN * 32 + 255) / 256, 256>>>(Wl2, bl2, Wr2, br2);
    k_edge2<<<(NN * 32 + 255) / 256, 256>>>(att2);
    k_agg2<<<(NN + 255) / 256, 256>>>(bias2, out);
}